// round 1
// baseline (speedup 1.0000x reference)
#include <cuda_runtime.h>
#include <math.h>

// Shapes (fixed by problem)
#define Kq    4096
#define Mq    4
#define Dq    32
#define HWq   1024
#define NMq   16          // N*M
#define NPOS  16384       // N*M*H*W
#define EPSF  1e-7f
#define NEGINF -1e9f

// Output layout: [sample | code | one_hot | logit], all float32
#define SAMPLE_OFF 0ull
#define CODE_OFF   67108864ull
#define ONEHOT_OFF 67125248ull
#define LOGIT_OFF  134234112ull

// Scratch (no cudaMalloc allowed)
__device__ float g_expo;
__device__ float g_thresh[Mq * Kq];
__device__ float g_c2[Mq * Kq];

// ---------------- Kernel 1: code_usage -> expo ----------------
__global__ void k_usage(const float* __restrict__ freq) {
    __shared__ int warpsum[8];
    int tid = threadIdx.x;
    int c = 0;
    for (int i = tid; i < Mq * Kq; i += 256) c += (freq[i] > EPSF) ? 1 : 0;
    for (int o = 16; o; o >>= 1) c += __shfl_down_sync(0xffffffffu, c, o);
    if ((tid & 31) == 0) warpsum[tid >> 5] = c;
    __syncthreads();
    if (tid == 0) {
        int t = 0;
        for (int w = 0; w < 8; ++w) t += warpsum[w];
        float cu = (float)t * (1.0f / 16384.0f);
        cu = fminf(fmaxf(cu, 0.0f), 1.0f);
        g_expo = 12.0f - 11.0f * (cu * cu);   // -(BITS-1)*cu^2 + BITS
    }
}

// ---------------- Kernel 2: thresh + codeword norms ----------------
__global__ void k_prep(const float* __restrict__ freq, const float* __restrict__ cb) {
    int i = blockIdx.x * blockDim.x + threadIdx.x;
    if (i >= Mq * Kq) return;
    const float* c = cb + (size_t)i * Dq;
    float s = 0.0f;
    #pragma unroll
    for (int d = 0; d < Dq; ++d) s += c[d] * c[d];
    g_c2[i] = s;
    float f = freq[i];
    float th = -1.0f;   // drop >= 0 always, so -1 means "never drop"
    if (f > 0.0f) {
        double ie = 1.0 / (double)g_expo;
        th = (float)pow((double)f, ie);   // drop^expo < f  <=>  drop < f^(1/expo)
    }
    g_thresh[i] = th;
}

// ---------------- Kernel 3: fused main ----------------
// grid = 2048 blocks, 512 threads. Block: one (n,m), 8 positions.
// Group g = tid/256 handles positions g*4 .. g*4+3; thread owns k = jj + c*256 + t*1024.
__global__ __launch_bounds__(512, 1) void k_main(
    const float* __restrict__ x, const float* __restrict__ cb,
    const float* __restrict__ temp,
    const float* __restrict__ drop, const float* __restrict__ gum,
    float* __restrict__ out)
{
    extern __shared__ float sm[];
    float* cbs     = sm;                   // 1024 * 33
    float* xvs     = sm + 1024 * 33;       // 8 * 32
    float* x2s     = xvs + 256;            // 8
    float* scV     = x2s + 8;              // 64 (logit argmax vals)
    float* scV2    = scV + 64;             // 64 (s argmax vals)
    float* scS     = scV2 + 64;            // 64 (exp sums)
    float* finSmax = scS + 64;             // 8
    float* finInv  = finSmax + 8;          // 8
    int*   scI     = (int*)(finInv + 8);   // 64
    int*   scI2    = scI + 64;             // 64
    int*   finSidx = scI2 + 64;            // 8
    int*   finLidx = finSidx + 8;          // 8

    const int tid  = threadIdx.x;
    const int bid  = blockIdx.x;
    const int nm   = bid >> 7;             // (n*M + m)
    const int m    = nm & 3;
    const int hw0  = (bid & 127) << 3;     // 8 positions per block
    const long posBase = (long)nm * HWq + hw0;

    const int g    = tid >> 8;             // 0/1
    const int jj   = tid & 255;
    const int wig  = (tid >> 5) & 7;       // warp within group
    const int lane = tid & 31;

    // Load x vectors for 8 positions (D strided by H*W in x)
    if (tid < 256) {
        int p = tid & 7, d = tid >> 3;
        xvs[p * 32 + d] = x[((size_t)(nm * Dq + d)) * HWq + hw0 + p];
    }
    __syncthreads();
    if (tid < 8) {
        float s = 0.0f;
        #pragma unroll
        for (int d = 0; d < 32; ++d) { float v = xvs[tid * 32 + d]; s += v * v; }
        x2s[tid] = s;
    }
    __syncthreads();

    const float lbt = fmaxf(temp[m], EPSF);       // lower_bound(temperature)
    const float4* cb4 = (const float4*)(cb + (size_t)m * Kq * Dq);
    const float* c2m = g_c2 + m * Kq;
    const float* thm = g_thresh + m * Kq;

    float sreg[4][16];                            // s = logit + gumbel cache
    float lmv[4], smv[4]; int lix[4], six[4];
    #pragma unroll
    for (int p = 0; p < 4; ++p) { lmv[p] = -3.4e38f; smv[p] = -3.4e38f; lix[p] = 0; six[p] = 0; }

    #pragma unroll
    for (int t = 0; t < 4; ++t) {
        __syncthreads();
        // Cooperative load of 1024-codeword tile into SMEM (stride 33 -> no conflicts)
        for (int idx = tid; idx < 1024 * 8; idx += 512) {
            int row = idx >> 3, d4 = idx & 7;
            float4 v = cb4[(size_t)(t * 1024 + row) * 8 + d4];
            float* dst = &cbs[row * 33 + (d4 << 2)];
            dst[0] = v.x; dst[1] = v.y; dst[2] = v.z; dst[3] = v.w;
        }
        __syncthreads();

        float acc[4][4];
        #pragma unroll
        for (int c = 0; c < 4; ++c)
            #pragma unroll
            for (int p = 0; p < 4; ++p) acc[c][p] = 0.0f;

        // Register-tiled dots: 4 k x 4 positions per thread
        #pragma unroll
        for (int dc = 0; dc < 8; ++dc) {
            float xvr[4][4];
            #pragma unroll
            for (int p = 0; p < 4; ++p)
                #pragma unroll
                for (int dd = 0; dd < 4; ++dd)
                    xvr[p][dd] = xvs[(g * 4 + p) * 32 + dc * 4 + dd];
            #pragma unroll
            for (int c = 0; c < 4; ++c) {
                const float* cr = &cbs[(c * 256 + jj) * 33 + dc * 4];
                #pragma unroll
                for (int dd = 0; dd < 4; ++dd) {
                    float cv = cr[dd];
                    #pragma unroll
                    for (int p = 0; p < 4; ++p)
                        acc[c][p] = fmaf(cv, xvr[p][dd], acc[c][p]);
                }
            }
        }

        // Epilogue: logit, drop mask, s, streaming logit write, running argmaxes
        #pragma unroll
        for (int c = 0; c < 4; ++c) {
            int k = t * 1024 + c * 256 + jj;
            float c2k = c2m[k];
            float th  = thm[k];
            #pragma unroll
            for (int p = 0; p < 4; ++p) {
                int pp = g * 4 + p;
                size_t off = ((size_t)(posBase + pp)) * Kq + k;
                float dist = (x2s[pp] + c2k) - 2.0f * acc[c][p];
                float lg = (dist * -0.015625f) * lbt;      // (-dist/64)*lb(temp)
                float dn = drop[off];
                if (dn < th) lg += NEGINF;
                float gn = gum[off];
                float s = lg + gn;
                out[LOGIT_OFF + off] = lg;
                if (lg > lmv[p]) { lmv[p] = lg; lix[p] = k; }
                if (s  > smv[p]) { smv[p] = s;  six[p] = k; }
                sreg[p][t * 4 + c] = s;
            }
        }
    }

    // Block-wide argmax reductions (tie -> lowest k, matching jnp.argmax)
    #pragma unroll
    for (int p = 0; p < 4; ++p) {
        int pp = g * 4 + p;
        float v = lmv[p]; int ix = lix[p];
        for (int o = 16; o; o >>= 1) {
            float ov = __shfl_down_sync(0xffffffffu, v, o);
            int   oi = __shfl_down_sync(0xffffffffu, ix, o);
            if (ov > v || (ov == v && oi < ix)) { v = ov; ix = oi; }
        }
        if (lane == 0) { scV[pp * 8 + wig] = v; scI[pp * 8 + wig] = ix; }
        v = smv[p]; ix = six[p];
        for (int o = 16; o; o >>= 1) {
            float ov = __shfl_down_sync(0xffffffffu, v, o);
            int   oi = __shfl_down_sync(0xffffffffu, ix, o);
            if (ov > v || (ov == v && oi < ix)) { v = ov; ix = oi; }
        }
        if (lane == 0) { scV2[pp * 8 + wig] = v; scI2[pp * 8 + wig] = ix; }
    }
    __syncthreads();
    if (tid < 8) {
        float bv = -3.4e38f; int bi = 0;
        for (int w = 0; w < 8; ++w) {
            float v = scV[tid * 8 + w]; int i2 = scI[tid * 8 + w];
            if (v > bv || (v == bv && i2 < bi)) { bv = v; bi = i2; }
        }
        finLidx[tid] = bi;
        bv = -3.4e38f; bi = 0;
        for (int w = 0; w < 8; ++w) {
            float v = scV2[tid * 8 + w]; int i2 = scI2[tid * 8 + w];
            if (v > bv || (v == bv && i2 < bi)) { bv = v; bi = i2; }
        }
        finSmax[tid] = bv; finSidx[tid] = bi;
    }
    __syncthreads();

    // Softmax denominator from the register-resident s cache
    #pragma unroll
    for (int p = 0; p < 4; ++p) {
        int pp = g * 4 + p;
        float mx = finSmax[pp];
        float s = 0.0f;
        #pragma unroll
        for (int i = 0; i < 16; ++i) s += __expf(sreg[p][i] - mx);
        for (int o = 16; o; o >>= 1) s += __shfl_down_sync(0xffffffffu, s, o);
        if (lane == 0) scS[pp * 8 + wig] = s;
    }
    __syncthreads();
    if (tid < 8) {
        float s = 0.0f;
        for (int w = 0; w < 8; ++w) s += scS[tid * 8 + w];
        finInv[tid] = 1.0f / s;
        out[CODE_OFF + (size_t)(posBase + tid)] = (float)finLidx[tid];
    }
    __syncthreads();

    // Write sample + one_hot (streaming, coalesced across jj)
    #pragma unroll
    for (int p = 0; p < 4; ++p) {
        int pp = g * 4 + p;
        float mx = finSmax[pp], inv = finInv[pp];
        int si = finSidx[pp], li = finLidx[pp];
        size_t base = ((size_t)(posBase + pp)) * Kq;
        #pragma unroll
        for (int t = 0; t < 4; ++t)
            #pragma unroll
            for (int c = 0; c < 4; ++c) {
                int k = t * 1024 + c * 256 + jj;
                float y = __expf(sreg[p][t * 4 + c] - mx) * inv;
                float hard = (k == si) ? 1.0f : 0.0f;
                out[SAMPLE_OFF + base + k] = (hard + y) - y;   // y_hard + y_soft - sg(y_soft)
                out[ONEHOT_OFF + base + k] = (k == li) ? 1.0f : 0.0f;
            }
    }
}

// ---------------- launch ----------------
extern "C" void kernel_launch(void* const* d_in, const int* in_sizes, int n_in,
                              void* d_out, int out_size) {
    const float* x    = (const float*)d_in[0];
    const float* cb   = (const float*)d_in[1];
    const float* freq = (const float*)d_in[2];
    const float* temp = (const float*)d_in[3];
    const float* drop = (const float*)d_in[4];
    const float* gum  = (const float*)d_in[5];
    float* out = (float*)d_out;

    const int smemBytes = (1024 * 33 + 256 + 8 + 64 * 3 + 8 * 2) * 4 + (64 * 2 + 8 * 2) * 4;
    cudaFuncSetAttribute(k_main, cudaFuncAttributeMaxDynamicSharedMemorySize, smemBytes);

    k_usage<<<1, 256>>>(freq);
    k_prep<<<64, 256>>>(freq, cb);
    k_main<<<2048, 512, smemBytes>>>(x, cb, temp, drop, gum, out);
}